// round 12
// baseline (speedup 1.0000x reference)
#include <cuda_runtime.h>
#include <cuda_fp16.h>
#include <cstdint>

// ---------------- problem constants ----------------
#define Nn     30000
#define F_IN   128
#define F_H    256
#define NHEAD  8
#define CCH    32
#define NEG_SLOPE 0.2f
#define EMAX   480000
#define SBLK   30          // scan blocks
#define SCHUNK 1000        // elements per scan block

// ---------------- device scratch (no allocs allowed) ----------------
__device__ float  g_h  [(size_t)Nn * F_H];
__device__ __half g_hf [(size_t)Nn * F_H];      // fp16 copy for the gather path
__device__ float  g_agg[(size_t)Nn * F_H];
__device__ float  g_x2 [(size_t)Nn * F_H];
__device__ float  g_as [(size_t)Nn * NHEAD];
__device__ float  g_ad [(size_t)Nn * NHEAD];
__device__ float  g_den[(size_t)Nn * NHEAD];
__device__ float  g_wT [(size_t)NHEAD * EMAX];  // head-major edge weights, CSR order
__device__ int    g_count [Nn];
__device__ int    g_rowptr[Nn + 1];
__device__ int    g_cursor[Nn];
__device__ int    g_bsum  [SBLK];
__device__ int    g_boff  [SBLK];
__device__ int2   g_cpair [EMAX + 1024];        // (src,dst) per CSR position

__device__ __forceinline__ void red4(float* p, float a, float b, float c, float d) {
    asm volatile("red.global.add.v4.f32 [%0], {%1,%2,%3,%4};"
                 :: "l"(p), "f"(a), "f"(b), "f"(c), "f"(d) : "memory");
}
__device__ __forceinline__ float leaky(float v) {
    return (v > 0.f) ? v : NEG_SLOPE * v;
}
__device__ __forceinline__ unsigned f2tf32(float f) {
    unsigned u;
    asm("cvt.rna.tf32.f32 %0, %1;" : "=r"(u) : "f"(f));
    return u;
}
__device__ __forceinline__ void mma_tf32(float c[4], const unsigned a[4], const unsigned b[2]) {
    asm volatile(
        "mma.sync.aligned.m16n8k8.row.col.f32.tf32.tf32.f32 "
        "{%0,%1,%2,%3}, {%4,%5,%6,%7}, {%8,%9}, {%0,%1,%2,%3};"
        : "+f"(c[0]), "+f"(c[1]), "+f"(c[2]), "+f"(c[3])
        : "r"(a[0]), "r"(a[1]), "r"(a[2]), "r"(a[3]), "r"(b[0]), "r"(b[1]));
}

// ---------------- tf32 MMA GEMM (double-buffered); also emits fp16 copy ----------------
#define AP 20
#define BP 136

template <int K>
__global__ void __launch_bounds__(256) k_gemm_tf32(const float* __restrict__ A,
                                                   const float* __restrict__ W,
                                                   float* __restrict__ Cout,
                                                   __half* __restrict__ Hout) {
    __shared__ unsigned As[128 * AP];
    __shared__ unsigned Bs[16 * BP];

    const int tid    = threadIdx.x;
    const int lane   = tid & 31;
    const int warpid = tid >> 5;
    const int row0   = blockIdx.y * 128;
    const int col0   = blockIdx.x * 128;
    const int wm     = (warpid & 3) * 32;
    const int wn     = (warpid >> 2) * 64;
    const int lg     = lane >> 2;
    const int lt     = lane & 3;

    float c[2][8][4];
#pragma unroll
    for (int t = 0; t < 2; t++)
#pragma unroll
        for (int j = 0; j < 8; j++)
#pragma unroll
            for (int r = 0; r < 4; r++) c[t][j][r] = 0.f;

    const int  a_row = tid >> 1;
    const int  a_c0  = (tid & 1) * 8;
    const int  b_k   = tid >> 4;
    const int  b_n0  = (tid & 15) * 4;
    const bool a_ok  = (row0 + a_row) < Nn;

    float4 a_reg[2], b_reg[2];
#pragma unroll
    for (int i = 0; i < 2; i++) {
        a_reg[i] = make_float4(0.f, 0.f, 0.f, 0.f);
        if (a_ok)
            a_reg[i] = *(const float4*)(A + (size_t)(row0 + a_row) * K + a_c0 + i * 4);
        b_reg[i] = *(const float4*)(W + (size_t)b_k * F_H + col0 + b_n0 + i * 64);
    }

    for (int k0 = 0; k0 < K; k0 += 16) {
#pragma unroll
        for (int i = 0; i < 2; i++) {
            float4 v = a_reg[i];
            *(uint4*)&As[a_row * AP + a_c0 + i * 4] =
                make_uint4(f2tf32(v.x), f2tf32(v.y), f2tf32(v.z), f2tf32(v.w));
            v = b_reg[i];
            *(uint4*)&Bs[b_k * BP + b_n0 + i * 64] =
                make_uint4(f2tf32(v.x), f2tf32(v.y), f2tf32(v.z), f2tf32(v.w));
        }
        __syncthreads();

        if (k0 + 16 < K) {
#pragma unroll
            for (int i = 0; i < 2; i++) {
                a_reg[i] = make_float4(0.f, 0.f, 0.f, 0.f);
                if (a_ok)
                    a_reg[i] = *(const float4*)(A + (size_t)(row0 + a_row) * K + k0 + 16 + a_c0 + i * 4);
                b_reg[i] = *(const float4*)(W + (size_t)(k0 + 16 + b_k) * F_H + col0 + b_n0 + i * 64);
            }
        }

#pragma unroll
        for (int kk = 0; kk < 16; kk += 8) {
            unsigned a[2][4];
#pragma unroll
            for (int t = 0; t < 2; t++) {
                int mr = wm + t * 16;
                a[t][0] = As[(mr + lg) * AP + kk + lt];
                a[t][1] = As[(mr + lg + 8) * AP + kk + lt];
                a[t][2] = As[(mr + lg) * AP + kk + lt + 4];
                a[t][3] = As[(mr + lg + 8) * AP + kk + lt + 4];
            }
#pragma unroll
            for (int j = 0; j < 8; j++) {
                unsigned b[2];
                int n = wn + j * 8 + lg;
                b[0] = Bs[(kk + lt) * BP + n];
                b[1] = Bs[(kk + lt + 4) * BP + n];
                mma_tf32(c[0][j], a[0], b);
                mma_tf32(c[1][j], a[1], b);
            }
        }
        __syncthreads();
    }

#pragma unroll
    for (int t = 0; t < 2; t++) {
        int r0 = row0 + wm + t * 16 + lg;
#pragma unroll
        for (int j = 0; j < 8; j++) {
            int cc = col0 + wn + j * 8 + lt * 2;
            if (r0 < Nn) {
                *(float2*)(Cout + (size_t)r0 * F_H + cc) = make_float2(c[t][j][0], c[t][j][1]);
                *(__half2*)(Hout + (size_t)r0 * F_H + cc) = __floats2half2_rn(c[t][j][0], c[t][j][1]);
            }
            if (r0 + 8 < Nn) {
                *(float2*)(Cout + (size_t)(r0 + 8) * F_H + cc) = make_float2(c[t][j][2], c[t][j][3]);
                *(__half2*)(Hout + (size_t)(r0 + 8) * F_H + cc) = __floats2half2_rn(c[t][j][2], c[t][j][3]);
            }
        }
    }
}

// ---------------- alpha projections ----------------
__global__ void k_alpha(const float* __restrict__ a_src, const float* __restrict__ a_dst) {
    int idx = blockIdx.x * blockDim.x + threadIdx.x;
    if (idx >= Nn * NHEAD) return;
    int n = idx >> 3, h = idx & 7;
    const float4* hp = (const float4*)(g_h + (size_t)n * F_H + h * CCH);
    const float4* as = (const float4*)(a_src + h * CCH);
    const float4* ad = (const float4*)(a_dst + h * CCH);
    float s = 0.f, d = 0.f;
#pragma unroll
    for (int i = 0; i < 8; i++) {
        float4 v = hp[i], a = as[i], b = ad[i];
        s += v.x * a.x + v.y * a.y + v.z * a.z + v.w * a.w;
        d += v.x * b.x + v.y * b.y + v.z * b.z + v.w * b.w;
    }
    g_as[idx] = s;
    g_ad[idx] = d;
}

// ---------------- CSR build ----------------
__global__ void k_zero_count() {
    int i = blockIdx.x * blockDim.x + threadIdx.x;
    if (i < Nn) g_count[i] = 0;
}
__global__ void k_count(const int* __restrict__ ei, int E) {
    int e = blockIdx.x * blockDim.x + threadIdx.x;
    if (e < E) atomicAdd(&g_count[ei[E + e]], 1);
}
__global__ void __launch_bounds__(1024) k_scan1() {
    __shared__ int red[32];
    int b = blockIdx.x, t = threadIdx.x;
    int v = (t < SCHUNK) ? g_count[b * SCHUNK + t] : 0;
#pragma unroll
    for (int o = 16; o > 0; o >>= 1) v += __shfl_down_sync(0xFFFFFFFFu, v, o);
    if ((t & 31) == 0) red[t >> 5] = v;
    __syncthreads();
    if (t < 32) {
        int s = red[t];
#pragma unroll
        for (int o = 16; o > 0; o >>= 1) s += __shfl_down_sync(0xFFFFFFFFu, s, o);
        if (t == 0) g_bsum[b] = s;
    }
}
__global__ void k_scan2() {
    int t = threadIdx.x;
    int v = (t < SBLK) ? g_bsum[t] : 0;
    int incl = v;
#pragma unroll
    for (int o = 1; o < 32; o <<= 1) {
        int u = __shfl_up_sync(0xFFFFFFFFu, incl, o);
        if (t >= o) incl += u;
    }
    if (t < SBLK) g_boff[t] = incl - v;
}
__global__ void __launch_bounds__(1024) k_scan3(int E) {
    __shared__ int sv[1024];
    int b = blockIdx.x, t = threadIdx.x;
    int c = (t < SCHUNK) ? g_count[b * SCHUNK + t] : 0;
    sv[t] = c;
    __syncthreads();
    for (int o = 1; o < 1024; o <<= 1) {
        int u = (t >= o) ? sv[t - o] : 0;
        __syncthreads();
        sv[t] += u;
        __syncthreads();
    }
    if (t < SCHUNK) {
        int excl = sv[t] - c + g_boff[b];
        g_rowptr[b * SCHUNK + t] = excl;
        g_cursor[b * SCHUNK + t] = excl;
    }
    if (b == SBLK - 1 && t == 0) g_rowptr[Nn] = E;
}
__global__ void k_scatter2(const int* __restrict__ ei, int E) {
    int e = blockIdx.x * blockDim.x + threadIdx.x;
    if (e >= E) return;
    int src = ei[e];
    int dst = ei[E + e];
    int pos = atomicAdd(&g_cursor[dst], 1);
    g_cpair[pos] = make_int2(src, dst);
}

// ---------------- zero agg ----------------
__global__ void k_zero_agg() {
    int i = blockIdx.x * blockDim.x + threadIdx.x;
    if (i < Nn * F_H) g_agg[i] = 0.f;
}

// ---------------- edge weights (head-major, CSR order) ----------------
__global__ void k_weights(int E) {
    int e = blockIdx.x * blockDim.x + threadIdx.x;
    if (e >= E) return;
    int2 p = g_cpair[e];
    float4 s0 = *(const float4*)(g_as + p.x * NHEAD);
    float4 s1 = *(const float4*)(g_as + p.x * NHEAD + 4);
    float4 d0 = *(const float4*)(g_ad + p.y * NHEAD);
    float4 d1 = *(const float4*)(g_ad + p.y * NHEAD + 4);
    g_wT[0 * (size_t)E + e] = __expf(leaky(s0.x + d0.x));
    g_wT[1 * (size_t)E + e] = __expf(leaky(s0.y + d0.y));
    g_wT[2 * (size_t)E + e] = __expf(leaky(s0.z + d0.z));
    g_wT[3 * (size_t)E + e] = __expf(leaky(s0.w + d0.w));
    g_wT[4 * (size_t)E + e] = __expf(leaky(s1.x + d1.x));
    g_wT[5 * (size_t)E + e] = __expf(leaky(s1.y + d1.y));
    g_wT[6 * (size_t)E + e] = __expf(leaky(s1.z + d1.z));
    g_wT[7 * (size_t)E + e] = __expf(leaky(s1.w + d1.w));
}

// ---------------- softmax denominators ----------------
__global__ void k_den(int E) {
    int idx = blockIdx.x * blockDim.x + threadIdx.x;
    if (idx >= Nn * NHEAD) return;
    int n = idx >> 3, h = idx & 7;
    int beg = g_rowptr[n], end = g_rowptr[n + 1];
    const float* wr = g_wT + (size_t)h * E;
    float a = 0.f, b = 0.f, c = 0.f, d = 0.f;
    int k = beg;
    for (; k + 4 <= end; k += 4) {
        a += wr[k]; b += wr[k + 1]; c += wr[k + 2]; d += wr[k + 3];
    }
    for (; k < end; k++) a += wr[k];
    g_den[idx] = (a + b) + (c + d);
}

// ---------------- CSR-ordered dedup push with fp16 gather ----------------
__global__ void __launch_bounds__(256) k_edge_csr(int E) {
    int tid = blockIdx.x * blockDim.x + threadIdx.x;
    int g = tid >> 3, j = tid & 7;
    int base = g * 8;
    unsigned mask = __ballot_sync(0xFFFFFFFFu, base < E);
    if (base >= E) return;
    int cnt = min(8, E - base);

    int s[8], d[8];
    float wl[8];
    if (cnt == 8) {
        const int4* pp = (const int4*)&g_cpair[base];
#pragma unroll
        for (int q = 0; q < 4; q++) {
            int4 pr = pp[q];
            s[q * 2] = pr.x; d[q * 2] = pr.y;
            s[q * 2 + 1] = pr.z; d[q * 2 + 1] = pr.w;
        }
        const float* wr = g_wT + (size_t)j * E + base;
        float4 w0 = *(const float4*)wr, w1 = *(const float4*)(wr + 4);
        wl[0] = w0.x; wl[1] = w0.y; wl[2] = w0.z; wl[3] = w0.w;
        wl[4] = w1.x; wl[5] = w1.y; wl[6] = w1.z; wl[7] = w1.w;
    } else {
#pragma unroll
        for (int p = 0; p < 8; p++) {
            int q = (p < cnt) ? base + p : base + cnt - 1;
            int2 pr = g_cpair[q];
            s[p] = pr.x;
            d[p] = pr.y;
            wl[p] = (p < cnt) ? g_wT[(size_t)j * E + q] : 0.f;
        }
    }

    float4 acc[8];
    int cur = d[0];
    {
        float wh[8];
#pragma unroll
        for (int i = 0; i < 8; i++) wh[i] = __shfl_sync(mask, wl[0], i, 8);
        const __half* hp = g_hf + (size_t)s[0] * F_H + j * 4;
#pragma unroll
        for (int i = 0; i < 8; i++) {
            uint2 raw = *(const uint2*)(hp + i * 32);
            float2 f01 = __half22float2(*(__half2*)&raw.x);
            float2 f23 = __half22float2(*(__half2*)&raw.y);
            acc[i] = make_float4(wh[i] * f01.x, wh[i] * f01.y, wh[i] * f23.x, wh[i] * f23.y);
        }
    }
#pragma unroll
    for (int p = 1; p < 8; p++) {
        float wh[8];
#pragma unroll
        for (int i = 0; i < 8; i++) wh[i] = __shfl_sync(mask, wl[p], i, 8);
        const __half* hp = g_hf + (size_t)s[p] * F_H + j * 4;
        if (d[p] != cur) {
            float* op = g_agg + (size_t)cur * F_H + j * 4;
#pragma unroll
            for (int i = 0; i < 8; i++)
                red4(op + i * 32, acc[i].x, acc[i].y, acc[i].z, acc[i].w);
            cur = d[p];
#pragma unroll
            for (int i = 0; i < 8; i++) {
                uint2 raw = *(const uint2*)(hp + i * 32);
                float2 f01 = __half22float2(*(__half2*)&raw.x);
                float2 f23 = __half22float2(*(__half2*)&raw.y);
                acc[i] = make_float4(wh[i] * f01.x, wh[i] * f01.y, wh[i] * f23.x, wh[i] * f23.y);
            }
        } else {
#pragma unroll
            for (int i = 0; i < 8; i++) {
                uint2 raw = *(const uint2*)(hp + i * 32);
                float2 f01 = __half22float2(*(__half2*)&raw.x);
                float2 f23 = __half22float2(*(__half2*)&raw.y);
                acc[i].x += wh[i] * f01.x; acc[i].y += wh[i] * f01.y;
                acc[i].z += wh[i] * f23.x; acc[i].w += wh[i] * f23.y;
            }
        }
    }
    float* op = g_agg + (size_t)cur * F_H + j * 4;
#pragma unroll
    for (int i = 0; i < 8; i++)
        red4(op + i * 32, acc[i].x, acc[i].y, acc[i].z, acc[i].w);
}

// ---------------- epilogue layer 1 ----------------
__global__ void k_elu1(const float* __restrict__ b) {
    int idx = blockIdx.x * blockDim.x + threadIdx.x;
    if (idx >= Nn * F_H) return;
    int n = idx >> 8, f = idx & 255, h = f >> 5;
    float ws = __expf(leaky(g_as[n * NHEAD + h] + g_ad[n * NHEAD + h]));
    float num = g_agg[idx] + ws * g_h[idx];
    float den = g_den[n * NHEAD + h] + ws;
    float v = num / den + b[f];
    g_x2[idx] = (v > 0.f) ? v : expm1f(v);
    g_agg[idx] = 0.f;
}

// ---------------- epilogue layer 2 + linear head ----------------
__global__ void k_final(const float* __restrict__ b2, const float* __restrict__ Wl,
                        const float* __restrict__ bl, float* __restrict__ out) {
    int gid = blockIdx.x * blockDim.x + threadIdx.x;
    int n = gid >> 5, lane = gid & 31;
    if (n >= Nn) return;
    float s = 0.f;
#pragma unroll
    for (int k = 0; k < 8; k++) {
        int f = lane + 32 * k;
        float ws = __expf(leaky(g_as[n * NHEAD + k] + g_ad[n * NHEAD + k]));
        float num = g_agg[(size_t)n * F_H + f] + ws * g_h[(size_t)n * F_H + f];
        float den = g_den[n * NHEAD + k] + ws;
        float v = num / den + b2[f];
        v = (v > 0.f) ? v : expm1f(v);
        s += v * Wl[f];
    }
#pragma unroll
    for (int o = 16; o > 0; o >>= 1) s += __shfl_down_sync(0xFFFFFFFFu, s, o);
    if (lane == 0) out[n] = s + bl[0];
}

// ---------------- host ----------------
extern "C" void kernel_launch(void* const* d_in, const int* in_sizes, int n_in,
                              void* d_out, int out_size) {
    const float* x   = (const float*)d_in[0];
    const int*   ei  = (const int*)  d_in[1];
    const float* W1  = (const float*)d_in[2];
    const float* a1s = (const float*)d_in[3];
    const float* a1d = (const float*)d_in[4];
    const float* b1  = (const float*)d_in[5];
    const float* W2  = (const float*)d_in[6];
    const float* a2s = (const float*)d_in[7];
    const float* a2d = (const float*)d_in[8];
    const float* b2  = (const float*)d_in[9];
    const float* Wl  = (const float*)d_in[10];
    const float* bl  = (const float*)d_in[11];
    float* out = (float*)d_out;

    const int E = in_sizes[1] / 2;          // 480000

    float*  g_h_p;  cudaGetSymbolAddress((void**)&g_h_p,  g_h);
    __half* g_hf_p; cudaGetSymbolAddress((void**)&g_hf_p, g_hf);
    float*  g_x2_p; cudaGetSymbolAddress((void**)&g_x2_p, g_x2);

    const int T = 256;
    dim3 gemm_grid(F_H / 128, (Nn + 127) / 128);
    int nh_blocks = (Nn * NHEAD + T - 1) / T;
    int e_blocks  = (E + T - 1) / T;
    int nf_blocks = (Nn * F_H + T - 1) / T;
    int fin_blocks = (Nn * 32 + T - 1) / T;

    // ---------- CSR build + zero agg (shared by both layers) ----------
    k_zero_agg<<<nf_blocks, T>>>();
    k_zero_count<<<(Nn + T - 1) / T, T>>>();
    k_count<<<e_blocks, T>>>(ei, E);
    k_scan1<<<SBLK, 1024>>>();
    k_scan2<<<1, 32>>>();
    k_scan3<<<SBLK, 1024>>>(E);
    k_scatter2<<<e_blocks, T>>>(ei, E);

    // ---------- layer 1 ----------
    k_gemm_tf32<F_IN><<<gemm_grid, T>>>(x, W1, g_h_p, g_hf_p);
    k_alpha<<<nh_blocks, T>>>(a1s, a1d);
    k_weights<<<e_blocks, T>>>(E);
    k_den<<<nh_blocks, T>>>(E);
    k_edge_csr<<<e_blocks, T>>>(E);
    k_elu1<<<nf_blocks, T>>>(b1);

    // ---------- layer 2 ----------
    k_gemm_tf32<F_H><<<gemm_grid, T>>>(g_x2_p, W2, g_h_p, g_hf_p);
    k_alpha<<<nh_blocks, T>>>(a2s, a2d);
    k_weights<<<e_blocks, T>>>(E);
    k_den<<<nh_blocks, T>>>(E);
    k_edge_csr<<<e_blocks, T>>>(E);
    k_final<<<fin_blocks, T>>>(b2, Wl, bl, out);
}

// round 13
// speedup vs baseline: 1.0563x; 1.0563x over previous
#include <cuda_runtime.h>
#include <cstdint>

// ---------------- problem constants ----------------
#define Nn     30000
#define F_IN   128
#define F_H    256
#define NHEAD  8
#define CCH    32
#define NEG_SLOPE 0.2f
#define EMAX   480000
#define SBLK   30          // scan blocks
#define SCHUNK 1000        // elements per scan block

// ---------------- device scratch (no allocs allowed) ----------------
__device__ float g_h  [(size_t)Nn * F_H];
__device__ float g_agg[(size_t)Nn * F_H];
__device__ float g_x2 [(size_t)Nn * F_H];
__device__ float g_as [(size_t)Nn * NHEAD];
__device__ float g_ad [(size_t)Nn * NHEAD];
__device__ float g_den1[(size_t)Nn * NHEAD];
__device__ float g_den2[(size_t)Nn * NHEAD];
__device__ float g_wT [(size_t)NHEAD * EMAX];   // head-major edge weights, CSR order
__device__ int   g_count [Nn];
__device__ int   g_rowptr[Nn + 1];
__device__ int   g_cursor[Nn];
__device__ int   g_bsum  [SBLK];
__device__ int   g_boff  [SBLK];
__device__ int2  g_cpair [EMAX + 1024];         // (src,dst) per CSR position

__device__ __forceinline__ void red4(float* p, float a, float b, float c, float d) {
    asm volatile("red.global.add.v4.f32 [%0], {%1,%2,%3,%4};"
                 :: "l"(p), "f"(a), "f"(b), "f"(c), "f"(d) : "memory");
}
__device__ __forceinline__ float leaky(float v) {
    return (v > 0.f) ? v : NEG_SLOPE * v;
}
__device__ __forceinline__ unsigned f2tf32(float f) {
    unsigned u;
    asm("cvt.rna.tf32.f32 %0, %1;" : "=r"(u) : "f"(f));
    return u;
}
__device__ __forceinline__ void mma_tf32(float c[4], const unsigned a[4], const unsigned b[2]) {
    asm volatile(
        "mma.sync.aligned.m16n8k8.row.col.f32.tf32.tf32.f32 "
        "{%0,%1,%2,%3}, {%4,%5,%6,%7}, {%8,%9}, {%0,%1,%2,%3};"
        : "+f"(c[0]), "+f"(c[1]), "+f"(c[2]), "+f"(c[3])
        : "r"(a[0]), "r"(a[1]), "r"(a[2]), "r"(a[3]), "r"(b[0]), "r"(b[1]));
}

// ---------------- tf32 MMA GEMM with register double-buffering ----------------
#define AP 20
#define BP 136

template <int K>
__global__ void __launch_bounds__(256) k_gemm_tf32(const float* __restrict__ A,
                                                   const float* __restrict__ W,
                                                   float* __restrict__ Cout) {
    __shared__ unsigned As[128 * AP];
    __shared__ unsigned Bs[16 * BP];

    const int tid    = threadIdx.x;
    const int lane   = tid & 31;
    const int warpid = tid >> 5;
    const int row0   = blockIdx.y * 128;
    const int col0   = blockIdx.x * 128;
    const int wm     = (warpid & 3) * 32;
    const int wn     = (warpid >> 2) * 64;
    const int lg     = lane >> 2;
    const int lt     = lane & 3;

    float c[2][8][4];
#pragma unroll
    for (int t = 0; t < 2; t++)
#pragma unroll
        for (int j = 0; j < 8; j++)
#pragma unroll
            for (int r = 0; r < 4; r++) c[t][j][r] = 0.f;

    const int  a_row = tid >> 1;
    const int  a_c0  = (tid & 1) * 8;
    const int  b_k   = tid >> 4;
    const int  b_n0  = (tid & 15) * 4;
    const bool a_ok  = (row0 + a_row) < Nn;

    float4 a_reg[2], b_reg[2];
#pragma unroll
    for (int i = 0; i < 2; i++) {
        a_reg[i] = make_float4(0.f, 0.f, 0.f, 0.f);
        if (a_ok)
            a_reg[i] = *(const float4*)(A + (size_t)(row0 + a_row) * K + a_c0 + i * 4);
        b_reg[i] = *(const float4*)(W + (size_t)b_k * F_H + col0 + b_n0 + i * 64);
    }

    for (int k0 = 0; k0 < K; k0 += 16) {
#pragma unroll
        for (int i = 0; i < 2; i++) {
            float4 v = a_reg[i];
            *(uint4*)&As[a_row * AP + a_c0 + i * 4] =
                make_uint4(f2tf32(v.x), f2tf32(v.y), f2tf32(v.z), f2tf32(v.w));
            v = b_reg[i];
            *(uint4*)&Bs[b_k * BP + b_n0 + i * 64] =
                make_uint4(f2tf32(v.x), f2tf32(v.y), f2tf32(v.z), f2tf32(v.w));
        }
        __syncthreads();

        if (k0 + 16 < K) {
#pragma unroll
            for (int i = 0; i < 2; i++) {
                a_reg[i] = make_float4(0.f, 0.f, 0.f, 0.f);
                if (a_ok)
                    a_reg[i] = *(const float4*)(A + (size_t)(row0 + a_row) * K + k0 + 16 + a_c0 + i * 4);
                b_reg[i] = *(const float4*)(W + (size_t)(k0 + 16 + b_k) * F_H + col0 + b_n0 + i * 64);
            }
        }

#pragma unroll
        for (int kk = 0; kk < 16; kk += 8) {
            unsigned a[2][4];
#pragma unroll
            for (int t = 0; t < 2; t++) {
                int mr = wm + t * 16;
                a[t][0] = As[(mr + lg) * AP + kk + lt];
                a[t][1] = As[(mr + lg + 8) * AP + kk + lt];
                a[t][2] = As[(mr + lg) * AP + kk + lt + 4];
                a[t][3] = As[(mr + lg + 8) * AP + kk + lt + 4];
            }
#pragma unroll
            for (int j = 0; j < 8; j++) {
                unsigned b[2];
                int n = wn + j * 8 + lg;
                b[0] = Bs[(kk + lt) * BP + n];
                b[1] = Bs[(kk + lt + 4) * BP + n];
                mma_tf32(c[0][j], a[0], b);
                mma_tf32(c[1][j], a[1], b);
            }
        }
        __syncthreads();
    }

#pragma unroll
    for (int t = 0; t < 2; t++) {
        int r0 = row0 + wm + t * 16 + lg;
#pragma unroll
        for (int j = 0; j < 8; j++) {
            int cc = col0 + wn + j * 8 + lt * 2;
            if (r0 < Nn)
                *(float2*)(Cout + (size_t)r0 * F_H + cc) = make_float2(c[t][j][0], c[t][j][1]);
            if (r0 + 8 < Nn)
                *(float2*)(Cout + (size_t)(r0 + 8) * F_H + cc) = make_float2(c[t][j][2], c[t][j][3]);
        }
    }
}

// ---------------- alpha projections ----------------
__global__ void k_alpha(const float* __restrict__ a_src, const float* __restrict__ a_dst) {
    int idx = blockIdx.x * blockDim.x + threadIdx.x;
    if (idx >= Nn * NHEAD) return;
    int n = idx >> 3, h = idx & 7;
    const float4* hp = (const float4*)(g_h + (size_t)n * F_H + h * CCH);
    const float4* as = (const float4*)(a_src + h * CCH);
    const float4* ad = (const float4*)(a_dst + h * CCH);
    float s = 0.f, d = 0.f;
#pragma unroll
    for (int i = 0; i < 8; i++) {
        float4 v = hp[i], a = as[i], b = ad[i];
        s += v.x * a.x + v.y * a.y + v.z * a.z + v.w * a.w;
        d += v.x * b.x + v.y * b.y + v.z * b.z + v.w * b.w;
    }
    g_as[idx] = s;
    g_ad[idx] = d;
}

// ---------------- CSR build ----------------
__global__ void k_zero_agg() {
    int i = blockIdx.x * blockDim.x + threadIdx.x;
    if (i < Nn * F_H) g_agg[i] = 0.f;
    if (i < Nn * NHEAD) { g_den1[i] = 0.f; g_den2[i] = 0.f; }
}
__global__ void k_zero_count() {
    int i = blockIdx.x * blockDim.x + threadIdx.x;
    if (i < Nn) g_count[i] = 0;
}
__global__ void k_count(const int* __restrict__ ei, int E) {
    int e = blockIdx.x * blockDim.x + threadIdx.x;
    if (e < E) atomicAdd(&g_count[ei[E + e]], 1);
}
__global__ void __launch_bounds__(1024) k_scan1() {
    __shared__ int red[32];
    int b = blockIdx.x, t = threadIdx.x;
    int v = (t < SCHUNK) ? g_count[b * SCHUNK + t] : 0;
#pragma unroll
    for (int o = 16; o > 0; o >>= 1) v += __shfl_down_sync(0xFFFFFFFFu, v, o);
    if ((t & 31) == 0) red[t >> 5] = v;
    __syncthreads();
    if (t < 32) {
        int s = red[t];
#pragma unroll
        for (int o = 16; o > 0; o >>= 1) s += __shfl_down_sync(0xFFFFFFFFu, s, o);
        if (t == 0) g_bsum[b] = s;
    }
}
__global__ void k_scan2() {
    int t = threadIdx.x;
    int v = (t < SBLK) ? g_bsum[t] : 0;
    int incl = v;
#pragma unroll
    for (int o = 1; o < 32; o <<= 1) {
        int u = __shfl_up_sync(0xFFFFFFFFu, incl, o);
        if (t >= o) incl += u;
    }
    if (t < SBLK) g_boff[t] = incl - v;
}
__global__ void __launch_bounds__(1024) k_scan3(int E) {
    __shared__ int sv[1024];
    int b = blockIdx.x, t = threadIdx.x;
    int c = (t < SCHUNK) ? g_count[b * SCHUNK + t] : 0;
    sv[t] = c;
    __syncthreads();
    for (int o = 1; o < 1024; o <<= 1) {
        int u = (t >= o) ? sv[t - o] : 0;
        __syncthreads();
        sv[t] += u;
        __syncthreads();
    }
    if (t < SCHUNK) {
        int excl = sv[t] - c + g_boff[b];
        g_rowptr[b * SCHUNK + t] = excl;
        g_cursor[b * SCHUNK + t] = excl;
    }
    if (b == SBLK - 1 && t == 0) g_rowptr[Nn] = E;
}
__global__ void k_scatter2(const int* __restrict__ ei, int E) {
    int e = blockIdx.x * blockDim.x + threadIdx.x;
    if (e >= E) return;
    int src = ei[e];
    int dst = ei[E + e];
    int pos = atomicAdd(&g_cursor[dst], 1);
    g_cpair[pos] = make_int2(src, dst);
}

// ---------------- edge weights (head-major, CSR order) + fused den atomics ----------------
__global__ void k_weights(int E, float* __restrict__ den) {
    int e = blockIdx.x * blockDim.x + threadIdx.x;
    if (e >= E) return;
    int2 p = g_cpair[e];
    float4 s0 = *(const float4*)(g_as + p.x * NHEAD);
    float4 s1 = *(const float4*)(g_as + p.x * NHEAD + 4);
    float4 d0 = *(const float4*)(g_ad + p.y * NHEAD);
    float4 d1 = *(const float4*)(g_ad + p.y * NHEAD + 4);
    float w0 = __expf(leaky(s0.x + d0.x));
    float w1 = __expf(leaky(s0.y + d0.y));
    float w2 = __expf(leaky(s0.z + d0.z));
    float w3 = __expf(leaky(s0.w + d0.w));
    float w4 = __expf(leaky(s1.x + d1.x));
    float w5 = __expf(leaky(s1.y + d1.y));
    float w6 = __expf(leaky(s1.z + d1.z));
    float w7 = __expf(leaky(s1.w + d1.w));
    g_wT[0 * (size_t)E + e] = w0;
    g_wT[1 * (size_t)E + e] = w1;
    g_wT[2 * (size_t)E + e] = w2;
    g_wT[3 * (size_t)E + e] = w3;
    g_wT[4 * (size_t)E + e] = w4;
    g_wT[5 * (size_t)E + e] = w5;
    g_wT[6 * (size_t)E + e] = w6;
    g_wT[7 * (size_t)E + e] = w7;
    float* dp = den + p.y * NHEAD;      // 32B-aligned, 8 consecutive floats
    red4(dp,     w0, w1, w2, w3);
    red4(dp + 4, w4, w5, w6, w7);
}

// ---------------- CSR-ordered dedup push (fp32 gather) ----------------
__global__ void __launch_bounds__(256) k_edge_csr(int E) {
    int tid = blockIdx.x * blockDim.x + threadIdx.x;
    int g = tid >> 3, j = tid & 7;
    int base = g * 8;
    unsigned mask = __ballot_sync(0xFFFFFFFFu, base < E);
    if (base >= E) return;
    int cnt = min(8, E - base);

    int s[8], d[8];
    float wl[8];
    if (cnt == 8) {
        const int4* pp = (const int4*)&g_cpair[base];
#pragma unroll
        for (int q = 0; q < 4; q++) {
            int4 pr = pp[q];
            s[q * 2] = pr.x; d[q * 2] = pr.y;
            s[q * 2 + 1] = pr.z; d[q * 2 + 1] = pr.w;
        }
        const float* wr = g_wT + (size_t)j * E + base;
        float4 w0 = *(const float4*)wr, w1 = *(const float4*)(wr + 4);
        wl[0] = w0.x; wl[1] = w0.y; wl[2] = w0.z; wl[3] = w0.w;
        wl[4] = w1.x; wl[5] = w1.y; wl[6] = w1.z; wl[7] = w1.w;
    } else {
#pragma unroll
        for (int p = 0; p < 8; p++) {
            int q = (p < cnt) ? base + p : base + cnt - 1;
            int2 pr = g_cpair[q];
            s[p] = pr.x;
            d[p] = pr.y;
            wl[p] = (p < cnt) ? g_wT[(size_t)j * E + q] : 0.f;
        }
    }

    float4 acc[8];
    int cur = d[0];
    {
        float wh[8];
#pragma unroll
        for (int i = 0; i < 8; i++) wh[i] = __shfl_sync(mask, wl[0], i, 8);
        const float4* hp = (const float4*)(g_h + (size_t)s[0] * F_H) + j;
#pragma unroll
        for (int i = 0; i < 8; i++) {
            float4 hv = __ldg(hp + i * 8);
            acc[i] = make_float4(wh[i] * hv.x, wh[i] * hv.y, wh[i] * hv.z, wh[i] * hv.w);
        }
    }
#pragma unroll
    for (int p = 1; p < 8; p++) {
        float wh[8];
#pragma unroll
        for (int i = 0; i < 8; i++) wh[i] = __shfl_sync(mask, wl[p], i, 8);
        const float4* hp = (const float4*)(g_h + (size_t)s[p] * F_H) + j;
        if (d[p] != cur) {
            float* op = g_agg + (size_t)cur * F_H + j * 4;
#pragma unroll
            for (int i = 0; i < 8; i++)
                red4(op + i * 32, acc[i].x, acc[i].y, acc[i].z, acc[i].w);
            cur = d[p];
#pragma unroll
            for (int i = 0; i < 8; i++) {
                float4 hv = __ldg(hp + i * 8);
                acc[i] = make_float4(wh[i] * hv.x, wh[i] * hv.y, wh[i] * hv.z, wh[i] * hv.w);
            }
        } else {
#pragma unroll
            for (int i = 0; i < 8; i++) {
                float4 hv = __ldg(hp + i * 8);
                acc[i].x += wh[i] * hv.x; acc[i].y += wh[i] * hv.y;
                acc[i].z += wh[i] * hv.z; acc[i].w += wh[i] * hv.w;
            }
        }
    }
    float* op = g_agg + (size_t)cur * F_H + j * 4;
#pragma unroll
    for (int i = 0; i < 8; i++)
        red4(op + i * 32, acc[i].x, acc[i].y, acc[i].z, acc[i].w);
}

// ---------------- epilogue layer 1 (self-loop fold, divide, bias, ELU; re-zero agg) ----
__global__ void k_elu1(const float* __restrict__ b) {
    int idx = blockIdx.x * blockDim.x + threadIdx.x;
    if (idx >= Nn * F_H) return;
    int n = idx >> 8, f = idx & 255, h = f >> 5;
    float ws = __expf(leaky(g_as[n * NHEAD + h] + g_ad[n * NHEAD + h]));
    float num = g_agg[idx] + ws * g_h[idx];
    float den = g_den1[n * NHEAD + h] + ws;
    float v = num / den + b[f];
    g_x2[idx] = (v > 0.f) ? v : expm1f(v);
    g_agg[idx] = 0.f;
}

// ---------------- epilogue layer 2 + linear head ----------------
__global__ void k_final(const float* __restrict__ b2, const float* __restrict__ Wl,
                        const float* __restrict__ bl, float* __restrict__ out) {
    int gid = blockIdx.x * blockDim.x + threadIdx.x;
    int n = gid >> 5, lane = gid & 31;
    if (n >= Nn) return;
    float s = 0.f;
#pragma unroll
    for (int k = 0; k < 8; k++) {
        int f = lane + 32 * k;
        float ws = __expf(leaky(g_as[n * NHEAD + k] + g_ad[n * NHEAD + k]));
        float num = g_agg[(size_t)n * F_H + f] + ws * g_h[(size_t)n * F_H + f];
        float den = g_den2[n * NHEAD + k] + ws;
        float v = num / den + b2[f];
        v = (v > 0.f) ? v : expm1f(v);
        s += v * Wl[f];
    }
#pragma unroll
    for (int o = 16; o > 0; o >>= 1) s += __shfl_down_sync(0xFFFFFFFFu, s, o);
    if (lane == 0) out[n] = s + bl[0];
}

// ---------------- host ----------------
extern "C" void kernel_launch(void* const* d_in, const int* in_sizes, int n_in,
                              void* d_out, int out_size) {
    const float* x   = (const float*)d_in[0];
    const int*   ei  = (const int*)  d_in[1];
    const float* W1  = (const float*)d_in[2];
    const float* a1s = (const float*)d_in[3];
    const float* a1d = (const float*)d_in[4];
    const float* b1  = (const float*)d_in[5];
    const float* W2  = (const float*)d_in[6];
    const float* a2s = (const float*)d_in[7];
    const float* a2d = (const float*)d_in[8];
    const float* b2  = (const float*)d_in[9];
    const float* Wl  = (const float*)d_in[10];
    const float* bl  = (const float*)d_in[11];
    float* out = (float*)d_out;

    const int E = in_sizes[1] / 2;          // 480000

    float* g_h_p;    cudaGetSymbolAddress((void**)&g_h_p,    g_h);
    float* g_x2_p;   cudaGetSymbolAddress((void**)&g_x2_p,   g_x2);
    float* g_den1_p; cudaGetSymbolAddress((void**)&g_den1_p, g_den1);
    float* g_den2_p; cudaGetSymbolAddress((void**)&g_den2_p, g_den2);

    const int T = 256;
    dim3 gemm_grid(F_H / 128, (Nn + 127) / 128);
    int nh_blocks = (Nn * NHEAD + T - 1) / T;
    int e_blocks  = (E + T - 1) / T;
    int nf_blocks = (Nn * F_H + T - 1) / T;
    int fin_blocks = (Nn * 32 + T - 1) / T;

    // ---------- prep; layer-1 GEMM placed at launch index 3 so ncu profiles it ----------
    k_zero_agg<<<nf_blocks, T>>>();                       // 0
    k_zero_count<<<(Nn + T - 1) / T, T>>>();              // 1
    k_count<<<e_blocks, T>>>(ei, E);                      // 2
    k_gemm_tf32<F_IN><<<gemm_grid, T>>>(x, W1, g_h_p);    // 3  <- profiled
    k_scan1<<<SBLK, 1024>>>();                            // 4
    k_scan2<<<1, 32>>>();                                 // 5
    k_scan3<<<SBLK, 1024>>>(E);                           // 6
    k_scatter2<<<e_blocks, T>>>(ei, E);                   // 7

    // ---------- layer 1 ----------
    k_alpha<<<nh_blocks, T>>>(a1s, a1d);
    k_weights<<<e_blocks, T>>>(E, g_den1_p);
    k_edge_csr<<<e_blocks, T>>>(E);
    k_elu1<<<nf_blocks, T>>>(b1);

    // ---------- layer 2 ----------
    k_gemm_tf32<F_H><<<gemm_grid, T>>>(g_x2_p, W2, g_h_p);
    k_alpha<<<nh_blocks, T>>>(a2s, a2d);
    k_weights<<<e_blocks, T>>>(E, g_den2_p);
    k_edge_csr<<<e_blocks, T>>>(E);
    k_final<<<fin_blocks, T>>>(b2, Wl, bl, out);
}

// round 14
// speedup vs baseline: 1.1468x; 1.0857x over previous
#include <cuda_runtime.h>
#include <cstdint>

// ---------------- problem constants ----------------
#define Nn     30000
#define F_IN   128
#define F_H    256
#define NHEAD  8
#define CCH    32
#define NEG_SLOPE 0.2f
#define EMAX   480000
#define SBLK   30          // scan blocks
#define SCHUNK 1000        // elements per scan block

// ---------------- device scratch (no allocs allowed) ----------------
__device__ float g_h  [(size_t)Nn * F_H];
__device__ float g_agg[(size_t)Nn * F_H];
__device__ float g_x2 [(size_t)Nn * F_H];
__device__ float g_as [(size_t)Nn * NHEAD];
__device__ float g_ad [(size_t)Nn * NHEAD];
__device__ float g_den1[(size_t)Nn * NHEAD];
__device__ float g_den2[(size_t)Nn * NHEAD];
__device__ int   g_count [Nn];
__device__ int   g_rowptr[Nn + 1];
__device__ int   g_cursor[Nn];
__device__ int   g_bsum  [SBLK];
__device__ int   g_boff  [SBLK];
__device__ int2  g_cpair [EMAX + 1024];         // (src,dst) per CSR position

__device__ __forceinline__ void red4(float* p, float a, float b, float c, float d) {
    asm volatile("red.global.add.v4.f32 [%0], {%1,%2,%3,%4};"
                 :: "l"(p), "f"(a), "f"(b), "f"(c), "f"(d) : "memory");
}
__device__ __forceinline__ void red1(float* p, float v) {
    asm volatile("red.global.add.f32 [%0], %1;" :: "l"(p), "f"(v) : "memory");
}
__device__ __forceinline__ float leaky(float v) {
    return (v > 0.f) ? v : NEG_SLOPE * v;
}
__device__ __forceinline__ unsigned f2tf32(float f) {
    unsigned u;
    asm("cvt.rna.tf32.f32 %0, %1;" : "=r"(u) : "f"(f));
    return u;
}
__device__ __forceinline__ void mma_tf32(float c[4], const unsigned a[4], const unsigned b[2]) {
    asm volatile(
        "mma.sync.aligned.m16n8k8.row.col.f32.tf32.tf32.f32 "
        "{%0,%1,%2,%3}, {%4,%5,%6,%7}, {%8,%9}, {%0,%1,%2,%3};"
        : "+f"(c[0]), "+f"(c[1]), "+f"(c[2]), "+f"(c[3])
        : "r"(a[0]), "r"(a[1]), "r"(a[2]), "r"(a[3]), "r"(b[0]), "r"(b[1]));
}

// ---------------- tf32 MMA GEMM with register double-buffering ----------------
#define AP 20
#define BP 136

template <int K>
__global__ void __launch_bounds__(256) k_gemm_tf32(const float* __restrict__ A,
                                                   const float* __restrict__ W,
                                                   float* __restrict__ Cout) {
    __shared__ unsigned As[128 * AP];
    __shared__ unsigned Bs[16 * BP];

    const int tid    = threadIdx.x;
    const int lane   = tid & 31;
    const int warpid = tid >> 5;
    const int row0   = blockIdx.y * 128;
    const int col0   = blockIdx.x * 128;
    const int wm     = (warpid & 3) * 32;
    const int wn     = (warpid >> 2) * 64;
    const int lg     = lane >> 2;
    const int lt     = lane & 3;

    float c[2][8][4];
#pragma unroll
    for (int t = 0; t < 2; t++)
#pragma unroll
        for (int j = 0; j < 8; j++)
#pragma unroll
            for (int r = 0; r < 4; r++) c[t][j][r] = 0.f;

    const int  a_row = tid >> 1;
    const int  a_c0  = (tid & 1) * 8;
    const int  b_k   = tid >> 4;
    const int  b_n0  = (tid & 15) * 4;
    const bool a_ok  = (row0 + a_row) < Nn;

    float4 a_reg[2], b_reg[2];
#pragma unroll
    for (int i = 0; i < 2; i++) {
        a_reg[i] = make_float4(0.f, 0.f, 0.f, 0.f);
        if (a_ok)
            a_reg[i] = *(const float4*)(A + (size_t)(row0 + a_row) * K + a_c0 + i * 4);
        b_reg[i] = *(const float4*)(W + (size_t)b_k * F_H + col0 + b_n0 + i * 64);
    }

    for (int k0 = 0; k0 < K; k0 += 16) {
#pragma unroll
        for (int i = 0; i < 2; i++) {
            float4 v = a_reg[i];
            *(uint4*)&As[a_row * AP + a_c0 + i * 4] =
                make_uint4(f2tf32(v.x), f2tf32(v.y), f2tf32(v.z), f2tf32(v.w));
            v = b_reg[i];
            *(uint4*)&Bs[b_k * BP + b_n0 + i * 64] =
                make_uint4(f2tf32(v.x), f2tf32(v.y), f2tf32(v.z), f2tf32(v.w));
        }
        __syncthreads();

        if (k0 + 16 < K) {
#pragma unroll
            for (int i = 0; i < 2; i++) {
                a_reg[i] = make_float4(0.f, 0.f, 0.f, 0.f);
                if (a_ok)
                    a_reg[i] = *(const float4*)(A + (size_t)(row0 + a_row) * K + k0 + 16 + a_c0 + i * 4);
                b_reg[i] = *(const float4*)(W + (size_t)(k0 + 16 + b_k) * F_H + col0 + b_n0 + i * 64);
            }
        }

#pragma unroll
        for (int kk = 0; kk < 16; kk += 8) {
            unsigned a[2][4];
#pragma unroll
            for (int t = 0; t < 2; t++) {
                int mr = wm + t * 16;
                a[t][0] = As[(mr + lg) * AP + kk + lt];
                a[t][1] = As[(mr + lg + 8) * AP + kk + lt];
                a[t][2] = As[(mr + lg) * AP + kk + lt + 4];
                a[t][3] = As[(mr + lg + 8) * AP + kk + lt + 4];
            }
#pragma unroll
            for (int j = 0; j < 8; j++) {
                unsigned b[2];
                int n = wn + j * 8 + lg;
                b[0] = Bs[(kk + lt) * BP + n];
                b[1] = Bs[(kk + lt + 4) * BP + n];
                mma_tf32(c[0][j], a[0], b);
                mma_tf32(c[1][j], a[1], b);
            }
        }
        __syncthreads();
    }

#pragma unroll
    for (int t = 0; t < 2; t++) {
        int r0 = row0 + wm + t * 16 + lg;
#pragma unroll
        for (int j = 0; j < 8; j++) {
            int cc = col0 + wn + j * 8 + lt * 2;
            if (r0 < Nn)
                *(float2*)(Cout + (size_t)r0 * F_H + cc) = make_float2(c[t][j][0], c[t][j][1]);
            if (r0 + 8 < Nn)
                *(float2*)(Cout + (size_t)(r0 + 8) * F_H + cc) = make_float2(c[t][j][2], c[t][j][3]);
        }
    }
}

// ---------------- alpha projections ----------------
__global__ void k_alpha(const float* __restrict__ a_src, const float* __restrict__ a_dst) {
    int idx = blockIdx.x * blockDim.x + threadIdx.x;
    if (idx >= Nn * NHEAD) return;
    int n = idx >> 3, h = idx & 7;
    const float4* hp = (const float4*)(g_h + (size_t)n * F_H + h * CCH);
    const float4* as = (const float4*)(a_src + h * CCH);
    const float4* ad = (const float4*)(a_dst + h * CCH);
    float s = 0.f, d = 0.f;
#pragma unroll
    for (int i = 0; i < 8; i++) {
        float4 v = hp[i], a = as[i], b = ad[i];
        s += v.x * a.x + v.y * a.y + v.z * a.z + v.w * a.w;
        d += v.x * b.x + v.y * b.y + v.z * b.z + v.w * b.w;
    }
    g_as[idx] = s;
    g_ad[idx] = d;
}

// ---------------- init ----------------
__global__ void k_zero_agg() {
    int i = blockIdx.x * blockDim.x + threadIdx.x;
    if (i < Nn * F_H) g_agg[i] = 0.f;
    if (i < Nn * NHEAD) { g_den1[i] = 0.f; g_den2[i] = 0.f; }
}
__global__ void k_zero_count() {
    int i = blockIdx.x * blockDim.x + threadIdx.x;
    if (i < Nn) g_count[i] = 0;
}
__global__ void k_count(const int* __restrict__ ei, int E) {
    int e = blockIdx.x * blockDim.x + threadIdx.x;
    if (e < E) atomicAdd(&g_count[ei[E + e]], 1);
}
__global__ void __launch_bounds__(1024) k_scan1() {
    __shared__ int red[32];
    int b = blockIdx.x, t = threadIdx.x;
    int v = (t < SCHUNK) ? g_count[b * SCHUNK + t] : 0;
#pragma unroll
    for (int o = 16; o > 0; o >>= 1) v += __shfl_down_sync(0xFFFFFFFFu, v, o);
    if ((t & 31) == 0) red[t >> 5] = v;
    __syncthreads();
    if (t < 32) {
        int s = red[t];
#pragma unroll
        for (int o = 16; o > 0; o >>= 1) s += __shfl_down_sync(0xFFFFFFFFu, s, o);
        if (t == 0) g_bsum[b] = s;
    }
}
__global__ void k_scan2() {
    int t = threadIdx.x;
    int v = (t < SBLK) ? g_bsum[t] : 0;
    int incl = v;
#pragma unroll
    for (int o = 1; o < 32; o <<= 1) {
        int u = __shfl_up_sync(0xFFFFFFFFu, incl, o);
        if (t >= o) incl += u;
    }
    if (t < SBLK) g_boff[t] = incl - v;
}
__global__ void __launch_bounds__(1024) k_scan3(int E) {
    __shared__ int sv[1024];
    int b = blockIdx.x, t = threadIdx.x;
    int c = (t < SCHUNK) ? g_count[b * SCHUNK + t] : 0;
    sv[t] = c;
    __syncthreads();
    for (int o = 1; o < 1024; o <<= 1) {
        int u = (t >= o) ? sv[t - o] : 0;
        __syncthreads();
        sv[t] += u;
        __syncthreads();
    }
    if (t < SCHUNK) {
        int excl = sv[t] - c + g_boff[b];
        g_rowptr[b * SCHUNK + t] = excl;
        g_cursor[b * SCHUNK + t] = excl;
    }
    if (b == SBLK - 1 && t == 0) g_rowptr[Nn] = E;
}
__global__ void k_scatter2(const int* __restrict__ ei, int E) {
    int e = blockIdx.x * blockDim.x + threadIdx.x;
    if (e >= E) return;
    int src = ei[e];
    int dst = ei[E + e];
    int pos = atomicAdd(&g_cursor[dst], 1);
    g_cpair[pos] = make_int2(src, dst);
}

// ---------------- fused CSR dedup push: weights + den + aggregate in one pass --------
// Group of 8 lanes handles 8 CSR positions. Lane j computes head-j weights for
// its 8 edges directly from g_as/g_ad; 8-wide shfl transposes to per-edge
// all-head weights. Same-dst runs accumulate acc (and den) in registers and
// flush via RED only on segment boundaries.
__global__ void __launch_bounds__(256) k_edge_csr(int E, float* __restrict__ den) {
    int tid = blockIdx.x * blockDim.x + threadIdx.x;
    int g = tid >> 3, j = tid & 7;
    int base = g * 8;
    unsigned mask = __ballot_sync(0xFFFFFFFFu, base < E);
    if (base >= E) return;
    int cnt = min(8, E - base);

    int s[8], d[8];
    if (cnt == 8) {
        const int4* pp = (const int4*)&g_cpair[base];
#pragma unroll
        for (int q = 0; q < 4; q++) {
            int4 pr = pp[q];
            s[q * 2] = pr.x;     d[q * 2] = pr.y;
            s[q * 2 + 1] = pr.z; d[q * 2 + 1] = pr.w;
        }
    } else {
#pragma unroll
        for (int p = 0; p < 8; p++) {
            int q = (p < cnt) ? base + p : base + cnt - 1;
            int2 pr = g_cpair[q];
            s[p] = pr.x;
            d[p] = pr.y;
        }
    }

    // head-j weights for the 8 edges (loads batched for MLP)
    float av[8], dv[8], wl[8];
#pragma unroll
    for (int p = 0; p < 8; p++) av[p] = __ldg(&g_as[s[p] * NHEAD + j]);
#pragma unroll
    for (int p = 0; p < 8; p++) dv[p] = __ldg(&g_ad[d[p] * NHEAD + j]);
#pragma unroll
    for (int p = 0; p < 8; p++) {
        float w = __expf(leaky(av[p] + dv[p]));
        wl[p] = (p < cnt) ? w : 0.f;            // padded edges contribute zero
    }

    float4 acc[8];
    float  dj;                                  // head-j den for current segment
    int cur = d[0];
    {
        float wh[8];
#pragma unroll
        for (int i = 0; i < 8; i++) wh[i] = __shfl_sync(mask, wl[0], i, 8);
        const float4* hp = (const float4*)(g_h + (size_t)s[0] * F_H) + j;
#pragma unroll
        for (int i = 0; i < 8; i++) {
            float4 hv = __ldg(hp + i * 8);
            acc[i] = make_float4(wh[i] * hv.x, wh[i] * hv.y, wh[i] * hv.z, wh[i] * hv.w);
        }
        dj = wl[0];
    }
#pragma unroll
    for (int p = 1; p < 8; p++) {
        float wh[8];
#pragma unroll
        for (int i = 0; i < 8; i++) wh[i] = __shfl_sync(mask, wl[p], i, 8);
        const float4* hp = (const float4*)(g_h + (size_t)s[p] * F_H) + j;
        if (d[p] != cur) {
            float* op = g_agg + (size_t)cur * F_H + j * 4;
#pragma unroll
            for (int i = 0; i < 8; i++)
                red4(op + i * 32, acc[i].x, acc[i].y, acc[i].z, acc[i].w);
            red1(&den[cur * NHEAD + j], dj);
            cur = d[p];
            dj = wl[p];
#pragma unroll
            for (int i = 0; i < 8; i++) {
                float4 hv = __ldg(hp + i * 8);
                acc[i] = make_float4(wh[i] * hv.x, wh[i] * hv.y, wh[i] * hv.z, wh[i] * hv.w);
            }
        } else {
            dj += wl[p];
#pragma unroll
            for (int i = 0; i < 8; i++) {
                float4 hv = __ldg(hp + i * 8);
                acc[i].x += wh[i] * hv.x; acc[i].y += wh[i] * hv.y;
                acc[i].z += wh[i] * hv.z; acc[i].w += wh[i] * hv.w;
            }
        }
    }
    float* op = g_agg + (size_t)cur * F_H + j * 4;
#pragma unroll
    for (int i = 0; i < 8; i++)
        red4(op + i * 32, acc[i].x, acc[i].y, acc[i].z, acc[i].w);
    red1(&den[cur * NHEAD + j], dj);
}

// ---------------- epilogue layer 1 (self-loop fold, divide, bias, ELU; re-zero agg) ----
__global__ void k_elu1(const float* __restrict__ b) {
    int idx = blockIdx.x * blockDim.x + threadIdx.x;
    if (idx >= Nn * F_H) return;
    int n = idx >> 8, f = idx & 255, h = f >> 5;
    float ws = __expf(leaky(g_as[n * NHEAD + h] + g_ad[n * NHEAD + h]));
    float num = g_agg[idx] + ws * g_h[idx];
    float den = g_den1[n * NHEAD + h] + ws;
    float v = num / den + b[f];
    g_x2[idx] = (v > 0.f) ? v : expm1f(v);
    g_agg[idx] = 0.f;
}

// ---------------- epilogue layer 2 + linear head ----------------
__global__ void k_final(const float* __restrict__ b2, const float* __restrict__ Wl,
                        const float* __restrict__ bl, float* __restrict__ out) {
    int gid = blockIdx.x * blockDim.x + threadIdx.x;
    int n = gid >> 5, lane = gid & 31;
    if (n >= Nn) return;
    float s = 0.f;
#pragma unroll
    for (int k = 0; k < 8; k++) {
        int f = lane + 32 * k;
        float ws = __expf(leaky(g_as[n * NHEAD + k] + g_ad[n * NHEAD + k]));
        float num = g_agg[(size_t)n * F_H + f] + ws * g_h[(size_t)n * F_H + f];
        float den = g_den2[n * NHEAD + k] + ws;
        float v = num / den + b2[f];
        v = (v > 0.f) ? v : expm1f(v);
        s += v * Wl[f];
    }
#pragma unroll
    for (int o = 16; o > 0; o >>= 1) s += __shfl_down_sync(0xFFFFFFFFu, s, o);
    if (lane == 0) out[n] = s + bl[0];
}

// ---------------- host ----------------
extern "C" void kernel_launch(void* const* d_in, const int* in_sizes, int n_in,
                              void* d_out, int out_size) {
    const float* x   = (const float*)d_in[0];
    const int*   ei  = (const int*)  d_in[1];
    const float* W1  = (const float*)d_in[2];
    const float* a1s = (const float*)d_in[3];
    const float* a1d = (const float*)d_in[4];
    const float* b1  = (const float*)d_in[5];
    const float* W2  = (const float*)d_in[6];
    const float* a2s = (const float*)d_in[7];
    const float* a2d = (const float*)d_in[8];
    const float* b2  = (const float*)d_in[9];
    const float* Wl  = (const float*)d_in[10];
    const float* bl  = (const float*)d_in[11];
    float* out = (float*)d_out;

    const int E = in_sizes[1] / 2;          // 480000

    float* g_h_p;    cudaGetSymbolAddress((void**)&g_h_p,    g_h);
    float* g_x2_p;   cudaGetSymbolAddress((void**)&g_x2_p,   g_x2);
    float* g_den1_p; cudaGetSymbolAddress((void**)&g_den1_p, g_den1);
    float* g_den2_p; cudaGetSymbolAddress((void**)&g_den2_p, g_den2);

    const int T = 256;
    dim3 gemm_grid(F_H / 128, (Nn + 127) / 128);
    int nh_blocks = (Nn * NHEAD + T - 1) / T;
    int e_blocks  = (E + T - 1) / T;
    int nf_blocks = (Nn * F_H + T - 1) / T;
    int fin_blocks = (Nn * 32 + T - 1) / T;

    // ---------- prep; layer-1 GEMM at launch index 3 (profiled slot) ----------
    k_zero_agg<<<nf_blocks, T>>>();                       // 0
    k_zero_count<<<(Nn + T - 1) / T, T>>>();              // 1
    k_count<<<e_blocks, T>>>(ei, E);                      // 2
    k_gemm_tf32<F_IN><<<gemm_grid, T>>>(x, W1, g_h_p);    // 3  <- profiled
    k_scan1<<<SBLK, 1024>>>();                            // 4
    k_scan2<<<1, 32>>>();                                 // 5
    k_scan3<<<SBLK, 1024>>>(E);                           // 6
    k_scatter2<<<e_blocks, T>>>(ei, E);                   // 7

    // ---------- layer 1 ----------
    k_alpha<<<nh_blocks, T>>>(a1s, a1d);
    k_edge_csr<<<e_blocks, T>>>(E, g_den1_p);
    k_elu1<<<nf_blocks, T>>>(b1);

    // ---------- layer 2 ----------
    k_gemm_tf32<F_H><<<gemm_grid, T>>>(g_x2_p, W2, g_h_p);
    k_alpha<<<nh_blocks, T>>>(a2s, a2d);
    k_edge_csr<<<e_blocks, T>>>(E, g_den2_p);
    k_final<<<fin_blocks, T>>>(b2, Wl, bl, out);
}